// round 15
// baseline (speedup 1.0000x reference)
#include <cuda_runtime.h>
#include <cuda_fp16.h>
#include <cstdint>

#define D 300
#define L 128
#define LT 124
#define KW 5

#define BCH   4864                         // one B chunk: 19 j x 32 lanes x 8 B
#define GSZ   82368                        // one G tile: 132 rows x 624 B
#define OFF_G0  1024
#define OFF_G1  (OFF_G0 + GSZ)             // 83392
#define OFF_B   (OFF_G1 + GSZ)             // 165760
#define OFF_RED (OFF_B + 6*BCH)            // 194944
#define SMEM_T  (OFF_RED + 2*2432)         // 199808

__device__ float d_cwT[KW*D*D];
__device__ float d_biasf[D];
__device__ __align__(16) __half d_WpkH[KW*2*19*19*32*4];   // fragment-order B (pads stay 0)
__device__ float d_conc[1024*600];         // [n][0..299] = cnn_out (+bias)

// ---------------- helpers ----------------
__device__ __forceinline__ uint32_t s2u(const void* p){
    uint32_t a; asm("{ .reg .u64 t; cvta.to.shared.u64 t, %1; cvt.u32.u64 %0, t; }":"=r"(a):"l"(p)); return a;
}
__device__ __forceinline__ void mma_f16(float* c, uint32_t a0, uint32_t a1,
                                        uint32_t a2, uint32_t a3,
                                        uint32_t b0, uint32_t b1){
    asm volatile("mma.sync.aligned.m16n8k16.row.col.f32.f16.f16.f32 "
        "{%0,%1,%2,%3}, {%4,%5,%6,%7}, {%8,%9}, {%0,%1,%2,%3};"
        : "+f"(c[0]),"+f"(c[1]),"+f"(c[2]),"+f"(c[3])
        : "r"(a0),"r"(a1),"r"(a2),"r"(a3),"r"(b0),"r"(b1));
}

// ---------------- prep: transpose conv_w (coalesced read) ----------------
__global__ void prep_kernel(const float* __restrict__ cw){
    int i = blockIdx.x*256 + threadIdx.x;
    if (i < KW*D*D){
        int k = i%KW, c = (i/KW)%D, o = i/(KW*D);
        d_cwT[(k*D+c)*D+o] = cw[i];
    }
}
__global__ void bias_kernel(const float* __restrict__ cw, const float* __restrict__ cb,
                            const float* __restrict__ b1){
    __shared__ float s[128];
    int o = blockIdx.x; float p = 0.f;
    for (int c = threadIdx.x; c < D; c += 128){
        const float* w = cw + ((size_t)o*D+c)*KW;
        p += b1[c]*(w[0]+w[1]+w[2]+w[3]+w[4]);
    }
    s[threadIdx.x] = p; __syncthreads();
    for (int st = 64; st; st >>= 1){
        if (threadIdx.x < st) s[threadIdx.x] += s[threadIdx.x+st];
        __syncthreads();
    }
    if (threadIdx.x == 0) d_biasf[o] = cb[o] + s[0];
}
// fuse + pack in one: Wf[k,d,o] = sum_c W1[d][c]*cwT[k][c][o], written straight
// into fragment order [k][oph][dc][j][lane][h]. Pad entries never written (zero-init).
__global__ void fuse_kernel(const float* __restrict__ W1){
    __shared__ float w1s[8][D];
    int k = blockIdx.x/38, d0 = (blockIdx.x%38)*8, tid = threadIdx.x;
    for (int i = tid; i < 8*D; i += blockDim.x){
        int q = i/D, c = i%D;
        w1s[q][c] = (d0+q < D) ? W1[(size_t)(d0+q)*D+c] : 0.f;
    }
    __syncthreads();
    if (tid < D){
        float a[8];
        #pragma unroll
        for (int q = 0; q < 8; q++) a[q] = 0.f;
        const float* ct = d_cwT + (size_t)k*D*D + tid;
        for (int c = 0; c < D; c++){
            float v = ct[(size_t)c*D];
            #pragma unroll
            for (int q = 0; q < 8; q++) a[q] = fmaf(w1s[q][c], v, a[q]);
        }
        const int o = tid, oph = (o >= 152), op = o - oph*152;
        const int j = op >> 3, r = op & 7;
        #pragma unroll
        for (int q = 0; q < 8; q++){
            int d = d0 + q;
            if (d < D){
                int dc = d >> 4, kk = d & 15;
                int q4 = (kk >> 1) & 3;
                int h  = (kk & 1) | ((kk >> 3) << 1);
                int lane = r*4 + q4;
                size_t idx = ((((size_t)(k*2 + oph)*19 + dc)*19 + j)*32 + lane)*4 + h;
                d_WpkH[idx] = __float2half_rn(a[q]);
            }
        }
    }
}

// ---------------- main: TWO bags per CTA, shared B stream ----------------
__device__ __forceinline__ void load_chunk(uint32_t sb, int oph, int c, int tid){
    int k = c/19, dc = c - k*19;
    const __half* src = d_WpkH + ((size_t)((k*2 + oph)*19 + dc))*2432;
    uint32_t dst = sb + OFF_B + (uint32_t)(c % 6)*BCH;
    #pragma unroll
    for (int u = 0; u < 2; u++){
        int i = tid + u*256;
        if (i < 304){
            asm volatile("cp.async.cg.shared.global [%0], [%1], 16;"
                         :: "r"(dst + (uint32_t)i*16), "l"(src + i*8) : "memory");
        }
    }
    asm volatile("cp.async.commit_group;" ::: "memory");
}

// m32 x (10|9 j) per warp, 2 bags: one B load feeds 4 MMAs
__device__ __forceinline__ void do_chunk(uint32_t sb, uint32_t g0, uint32_t g1,
                                         int c, float (*acc)[2][2][4], int lane,
                                         int jb, int gs){
    const int k = c/19, dcb = (c - k*19)*32;
    uint32_t ga0 = g0 + (uint32_t)(k*624 + dcb);
    uint32_t ga1 = g1 + (uint32_t)(k*624 + dcb);
    uint32_t A[2][4], E[2][4];
    asm volatile("ldmatrix.sync.aligned.m8n8.x4.shared.b16 {%0,%1,%2,%3}, [%4];"
                 : "=r"(A[0][0]),"=r"(A[0][1]),"=r"(A[0][2]),"=r"(A[0][3]) : "r"(ga0));
    asm volatile("ldmatrix.sync.aligned.m8n8.x4.shared.b16 {%0,%1,%2,%3}, [%4];"
                 : "=r"(E[0][0]),"=r"(E[0][1]),"=r"(E[0][2]),"=r"(E[0][3]) : "r"(ga0 + 16*624));
    asm volatile("ldmatrix.sync.aligned.m8n8.x4.shared.b16 {%0,%1,%2,%3}, [%4];"
                 : "=r"(A[1][0]),"=r"(A[1][1]),"=r"(A[1][2]),"=r"(A[1][3]) : "r"(ga1));
    asm volatile("ldmatrix.sync.aligned.m8n8.x4.shared.b16 {%0,%1,%2,%3}, [%4];"
                 : "=r"(E[1][0]),"=r"(E[1][1]),"=r"(E[1][2]),"=r"(E[1][3]) : "r"(ga1 + 16*624));
    uint32_t bb = sb + OFF_B + (uint32_t)(c % 6)*BCH + (uint32_t)lane*8
                             + (uint32_t)jb*256;
    #pragma unroll
    for (int t = 0; t < 10; t++) if (t < gs){
        uint32_t b0, b1;
        asm volatile("ld.shared.v2.b32 {%0,%1}, [%2];"
                     : "=r"(b0), "=r"(b1) : "r"(bb + (uint32_t)t*256));
        mma_f16(acc[t][0][0], A[0][0], A[0][1], A[0][2], A[0][3], b0, b1);
        mma_f16(acc[t][0][1], E[0][0], E[0][1], E[0][2], E[0][3], b0, b1);
        mma_f16(acc[t][1][0], A[1][0], A[1][1], A[1][2], A[1][3], b0, b1);
        mma_f16(acc[t][1][1], E[1][0], E[1][1], E[1][2], E[1][3], b0, b1);
    }
}

__global__ void __launch_bounds__(256,1)
main_kernel(const int* __restrict__ tok, const float* __restrict__ emb){
    extern __shared__ char sm[];
    const uint32_t sb = s2u(sm);
    const int n0 = blockIdx.x*2 + 0;       // two bags: n0, n0+1
    const int oph = 0;                      // both oph phases done sequentially below
    (void)oph;
    const int tid = threadIdx.x, wid = tid>>5, lane = tid&31;
    const int mw = wid & 3, ng = wid >> 2;
    const int jb = ng*10, gs = 10 - ng;     // j in [jb, jb+gs)

    // prefetch oph0 chunks 0..3 immediately (independent of G)
    load_chunk(sb, 0, 0, tid);
    load_chunk(sb, 0, 1, tid);
    load_chunk(sb, 0, 2, tid);
    load_chunk(sb, 0, 3, tid);

    if (tid < 2*L) ((int*)sm)[tid] = tok[n0*L + tid];
    // zero pads for both G tiles: rows 0..127 halves 300..311, rows 128..131 full
    for (int i = tid; i < 2*128*6; i += 256){
        int b = i / (128*6), rr = i % (128*6);
        int r = rr/6, w = rr - r*6;
        *(uint32_t*)(sm + OFF_G0 + (uint32_t)b*GSZ + (uint32_t)(r*156 + 150 + w)*4) = 0u;
    }
    for (int i = tid; i < 2*4*156; i += 256){
        int b = i / (4*156), rr = i % (4*156);
        *(uint32_t*)(sm + OFF_G0 + (uint32_t)b*GSZ + (uint32_t)(128*156 + rr)*4) = 0u;
    }
    __syncthreads();

    // gather both G tiles (fp32 -> fp16), row stride 624 B
    {
        const int* stok = (const int*)sm;
        for (int i = tid; i < 2*128*75; i += 256){
            int b = i / 9600, rr = i % 9600;
            int r = rr/75, q = rr - r*75;
            float4 v = __ldg((const float4*)(emb + (size_t)stok[b*128 + r]*D) + q);
            uint2 t;
            __half2 h01 = __floats2half2_rn(v.x, v.y);
            __half2 h23 = __floats2half2_rn(v.z, v.w);
            t.x = *(uint32_t*)&h01; t.y = *(uint32_t*)&h23;
            *(uint2*)(sm + OFF_G0 + (uint32_t)b*GSZ + (uint32_t)r*624 + (uint32_t)q*8) = t;
        }
    }

    const int r = lane >> 2;
    const uint32_t glane = (uint32_t)(mw*32 + (lane & 15))*624 + (uint32_t)((lane >> 4) << 4);
    const uint32_t g0 = sb + OFF_G0 + glane;
    const uint32_t g1 = sb + OFF_G1 + glane;
    float* red = (float*)(sm + OFF_RED);

    for (int ophase = 0; ophase < 2; ophase++){
        float acc[10][2][2][4];
        #pragma unroll
        for (int t = 0; t < 10; t++)
            #pragma unroll
            for (int b = 0; b < 2; b++)
                #pragma unroll
                for (int mt = 0; mt < 2; mt++)
                    acc[t][b][mt][0] = acc[t][b][mt][1] =
                    acc[t][b][mt][2] = acc[t][b][mt][3] = 0.f;

        for (int p = 0; p < 47; p++){
            if (p < 46) asm volatile("cp.async.wait_group 2;" ::: "memory");
            else        asm volatile("cp.async.wait_group 1;" ::: "memory");
            __syncthreads();
            if (p < 45){
                load_chunk(sb, ophase, 2*p + 4, tid);
                load_chunk(sb, ophase, 2*p + 5, tid);
            } else if (p == 45){
                load_chunk(sb, ophase, 94, tid);
            }
            do_chunk(sb, g0, g1, 2*p,     acc, lane, jb, gs);
            do_chunk(sb, g0, g1, 2*p + 1, acc, lane, jb, gs);
        }
        // tail chunk 94
        asm volatile("cp.async.wait_group 0;" ::: "memory");
        __syncthreads();
        do_chunk(sb, g0, g1, 94, acc, lane, jb, gs);
        __syncthreads();

        // prefetch next phase's chunks 0..3 (slots 0..3; red overlays nothing — own space)
        if (ophase == 0){
            load_chunk(sb, 1, 0, tid);
            load_chunk(sb, 1, 1, tid);
            load_chunk(sb, 1, 2, tid);
            load_chunk(sb, 1, 3, tid);
        }

        // ---- maxpool over t, per bag ----
        bool v2 = (mw*32 + 24 + r) < LT;
        #pragma unroll
        for (int b = 0; b < 2; b++){
            #pragma unroll
            for (int t = 0; t < 10; t++) if (t < gs){
                float m0 = fmaxf(acc[t][b][0][0], acc[t][b][0][2]);
                float m1 = fmaxf(acc[t][b][0][1], acc[t][b][0][3]);
                m0 = fmaxf(m0, fmaxf(acc[t][b][1][0], v2 ? acc[t][b][1][2] : -3.4e38f));
                m1 = fmaxf(m1, fmaxf(acc[t][b][1][1], v2 ? acc[t][b][1][3] : -3.4e38f));
                #pragma unroll
                for (int off = 4; off <= 16; off <<= 1){
                    m0 = fmaxf(m0, __shfl_xor_sync(0xffffffffu, m0, off));
                    m1 = fmaxf(m1, __shfl_xor_sync(0xffffffffu, m1, off));
                }
                if (lane < 4){
                    red[b*608 + mw*152 + (jb + t)*8 + 2*lane]     = m0;
                    red[b*608 + mw*152 + (jb + t)*8 + 2*lane + 1] = m1;
                }
            }
        }
        __syncthreads();
        #pragma unroll
        for (int b = 0; b < 2; b++){
            if (tid < 152){
                const float* rb = red + b*608;
                float m = fmaxf(fmaxf(rb[tid], rb[152 + tid]),
                                fmaxf(rb[304 + tid], rb[456 + tid]));
                int o = ophase*152 + tid;
                if (o < D) d_conc[(size_t)(n0 + b)*600 + o] = m + d_biasf[o];
            }
        }
        __syncthreads();
    }
}

// ---------------- MLP epilogue: 4 bags per CTA, 320 threads (1 o per thread) ----------------
__global__ void __launch_bounds__(320,1)
mlp_kernel(const float* __restrict__ mention,
           const float* __restrict__ W2, const float* __restrict__ b2,
           const float* __restrict__ W3, const float* __restrict__ b3,
           float* __restrict__ out){
    __shared__ float cs[4*600], hs[4*300];
    const int nb = blockIdx.x*4, tid = threadIdx.x;
    for (int i = tid; i < 1200; i += 320){
        int b = i/300, o = i - b*300;
        cs[b*600 + o]       = d_conc[(size_t)(nb+b)*600 + o];
        cs[b*600 + 300 + o] = mention[(size_t)(nb+b)*300 + o];
    }
    __syncthreads();
    if (tid < D){
        const int o = tid;
        float a0 = b2[o], a1 = a0, a2 = a0, a3 = a0;
        for (int j = 0; j < 600; j++){
            float w = __ldg(&W2[(size_t)j*D + o]);
            a0 = fmaf(cs[j], w, a0);       a1 = fmaf(cs[600+j], w, a1);
            a2 = fmaf(cs[1200+j], w, a2);  a3 = fmaf(cs[1800+j], w, a3);
        }
        hs[o] = tanhf(a0); hs[300+o] = tanhf(a1);
        hs[600+o] = tanhf(a2); hs[900+o] = tanhf(a3);
    }
    __syncthreads();
    if (tid < D){
        const int o = tid;
        float a0 = b3[o], a1 = a0, a2 = a0, a3 = a0;
        for (int j = 0; j < D; j++){
            float w = __ldg(&W3[(size_t)j*D + o]);
            a0 = fmaf(hs[j], w, a0);      a1 = fmaf(hs[300+j], w, a1);
            a2 = fmaf(hs[600+j], w, a2);  a3 = fmaf(hs[900+j], w, a3);
        }
        out[(size_t)nb*D + o] = a0;       out[(size_t)(nb+1)*D + o] = a1;
        out[(size_t)(nb+2)*D + o] = a2;   out[(size_t)(nb+3)*D + o] = a3;
    }
}

extern "C" void kernel_launch(void* const* d_in, const int* in_sizes, int n_in,
                              void* d_out, int out_size){
    const int*   tok     = (const int*)  d_in[0];
    const float* mention = (const float*)d_in[1];
    const float* emb     = (const float*)d_in[2];
    const float* W1      = (const float*)d_in[3];
    const float* b1      = (const float*)d_in[4];
    const float* conv_w  = (const float*)d_in[5];
    const float* conv_b  = (const float*)d_in[6];
    const float* W2      = (const float*)d_in[7];
    const float* b2      = (const float*)d_in[8];
    const float* W3      = (const float*)d_in[9];
    const float* b3      = (const float*)d_in[10];
    float* out = (float*)d_out;

    cudaFuncSetAttribute(main_kernel, cudaFuncAttributeMaxDynamicSharedMemorySize, SMEM_T);
    prep_kernel<<<(KW*D*D + 255)/256, 256>>>(conv_w);
    bias_kernel<<<D, 128>>>(conv_w, conv_b, b1);
    fuse_kernel<<<KW*38, 320>>>(W1);
    main_kernel<<<512, 256, SMEM_T>>>(tok, emb);
    mlp_kernel<<<256, 320>>>(mention, W2, b2, W3, b3, out);
}

// round 16
// speedup vs baseline: 1.3304x; 1.3304x over previous
#include <cuda_runtime.h>
#include <cuda_fp16.h>
#include <cstdint>

#define D 300
#define L 128
#define LT 124
#define KW 5

#define BCH   4864                         // one B chunk: 19 j x 32 lanes x 8 B
#define OFF_G   512
#define OFF_B   (OFF_G + 132*624)          // 82880
#define OFF_RED (OFF_B + 4*BCH)            // red overlays ring slots 4..5
#define SMEM_T  (OFF_B + 6*BCH)            // 112064

__device__ float d_cwT[KW*D*D];
__device__ float d_biasf[D];
__device__ __align__(16) __half d_WpkH[KW*2*19*19*32*4];   // fragment-order B (pads stay 0)
__device__ float d_conc[1024*600];         // [n][0..299] = cnn_out (+bias)

// ---------------- helpers ----------------
__device__ __forceinline__ uint32_t s2u(const void* p){
    uint32_t a; asm("{ .reg .u64 t; cvta.to.shared.u64 t, %1; cvt.u32.u64 %0, t; }":"=r"(a):"l"(p)); return a;
}
__device__ __forceinline__ void ldB(uint32_t a, uint32_t& x, uint32_t& y){
    asm("ld.shared.v2.b32 {%0,%1}, [%2];" : "=r"(x), "=r"(y) : "r"(a));
}
__device__ __forceinline__ void ldmat(uint32_t a, uint32_t* r){
    asm("ldmatrix.sync.aligned.m8n8.x4.shared.b16 {%0,%1,%2,%3}, [%4];"
        : "=r"(r[0]),"=r"(r[1]),"=r"(r[2]),"=r"(r[3]) : "r"(a));
}
__device__ __forceinline__ void mma_f16(float* c, uint32_t a0, uint32_t a1,
                                        uint32_t a2, uint32_t a3,
                                        uint32_t b0, uint32_t b1){
    asm volatile("mma.sync.aligned.m16n8k16.row.col.f32.f16.f16.f32 "
        "{%0,%1,%2,%3}, {%4,%5,%6,%7}, {%8,%9}, {%0,%1,%2,%3};"
        : "+f"(c[0]),"+f"(c[1]),"+f"(c[2]),"+f"(c[3])
        : "r"(a0),"r"(a1),"r"(a2),"r"(a3),"r"(b0),"r"(b1));
}

// ---------------- prep: transpose conv_w (coalesced read) ----------------
__global__ void prep_kernel(const float* __restrict__ cw){
    int i = blockIdx.x*256 + threadIdx.x;
    if (i < KW*D*D){
        int k = i%KW, c = (i/KW)%D, o = i/(KW*D);
        d_cwT[(k*D+c)*D+o] = cw[i];
    }
}
__global__ void bias_kernel(const float* __restrict__ cw, const float* __restrict__ cb,
                            const float* __restrict__ b1){
    __shared__ float s[128];
    int o = blockIdx.x; float p = 0.f;
    for (int c = threadIdx.x; c < D; c += 128){
        const float* w = cw + ((size_t)o*D+c)*KW;
        p += b1[c]*(w[0]+w[1]+w[2]+w[3]+w[4]);
    }
    s[threadIdx.x] = p; __syncthreads();
    for (int st = 64; st; st >>= 1){
        if (threadIdx.x < st) s[threadIdx.x] += s[threadIdx.x+st];
        __syncthreads();
    }
    if (threadIdx.x == 0) d_biasf[o] = cb[o] + s[0];
}
// fuse + pack in one: Wf[k,d,o] = sum_c W1[d][c]*cwT[k][c][o], written straight
// into fragment order [k][oph][dc][j][lane][h]. Pad entries never written (zero-init).
__global__ void fuse_kernel(const float* __restrict__ W1){
    __shared__ float w1s[8][D];
    int k = blockIdx.x/38, d0 = (blockIdx.x%38)*8, tid = threadIdx.x;
    for (int i = tid; i < 8*D; i += blockDim.x){
        int q = i/D, c = i%D;
        w1s[q][c] = (d0+q < D) ? W1[(size_t)(d0+q)*D+c] : 0.f;
    }
    __syncthreads();
    if (tid < D){
        float a[8];
        #pragma unroll
        for (int q = 0; q < 8; q++) a[q] = 0.f;
        const float* ct = d_cwT + (size_t)k*D*D + tid;
        for (int c = 0; c < D; c++){
            float v = ct[(size_t)c*D];
            #pragma unroll
            for (int q = 0; q < 8; q++) a[q] = fmaf(w1s[q][c], v, a[q]);
        }
        const int o = tid, oph = (o >= 152), op = o - oph*152;
        const int j = op >> 3, r = op & 7;
        #pragma unroll
        for (int q = 0; q < 8; q++){
            int d = d0 + q;
            if (d < D){
                int dc = d >> 4, kk = d & 15;
                int q4 = (kk >> 1) & 3;
                int h  = (kk & 1) | ((kk >> 3) << 1);
                int lane = r*4 + q4;
                size_t idx = ((((size_t)(k*2 + oph)*19 + dc)*19 + j)*32 + lane)*4 + h;
                d_WpkH[idx] = __float2half_rn(a[q]);
            }
        }
    }
}

// ---------------- main ----------------
__device__ __forceinline__ void load_chunk(uint32_t sb, int oph, int c, int tid){
    int k = c/19, dc = c - k*19;
    const __half* src = d_WpkH + ((size_t)((k*2 + oph)*19 + dc))*2432;
    uint32_t dst = sb + OFF_B + (uint32_t)(c % 6)*BCH;
    #pragma unroll
    for (int u = 0; u < 2; u++){
        int i = tid + u*256;
        if (i < 304){
            asm volatile("cp.async.cg.shared.global [%0], [%1], 16;"
                         :: "r"(dst + (uint32_t)i*16), "l"(src + i*8) : "memory");
        }
    }
    asm volatile("cp.async.commit_group;" ::: "memory");
}

// m32 x GS j per warp, software-pipelined B (load t+1 before MMAs of t)
template<int GS>
__device__ __forceinline__ void do_chunk_t(uint32_t sb, uint32_t gbase, int c,
                                           float (*acc)[2][4], int lane, int jb){
    const int k = c/19, dcb = (c - k*19)*32;
    uint32_t ga = gbase + (uint32_t)(k*624 + dcb);
    uint32_t A[4], E[4];
    ldmat(ga, A);
    ldmat(ga + 16*624, E);
    uint32_t bb = sb + OFF_B + (uint32_t)(c % 6)*BCH + (uint32_t)lane*8
                             + (uint32_t)jb*256;
    uint32_t br[2][2];
    ldB(bb, br[0][0], br[0][1]);
    #pragma unroll
    for (int t = 0; t < GS; t++){
        if (t + 1 < GS)
            ldB(bb + (uint32_t)(t+1)*256, br[(t+1)&1][0], br[(t+1)&1][1]);
        mma_f16(acc[t][0], A[0],A[1],A[2],A[3], br[t&1][0], br[t&1][1]);
        mma_f16(acc[t][1], E[0],E[1],E[2],E[3], br[t&1][0], br[t&1][1]);
    }
}

__global__ void __launch_bounds__(256,2)
main_kernel(const int* __restrict__ tok, const float* __restrict__ emb){
    extern __shared__ char sm[];
    const uint32_t sb = s2u(sm);
    const int n = blockIdx.x, tid = threadIdx.x, wid = tid>>5, lane = tid&31;
    const int mw = wid & 3, ng = wid >> 2;
    const int jb = ng*10, gs = 10 - ng;          // j in [jb, jb+gs)

    // prefetch oph0 chunks 0..3 immediately (independent of G)
    load_chunk(sb, 0, 0, tid);
    load_chunk(sb, 0, 1, tid);
    load_chunk(sb, 0, 2, tid);
    load_chunk(sb, 0, 3, tid);

    if (tid < L) ((int*)sm)[tid] = tok[n*L + tid];
    // zero pads: rows 0..127 halves 300..311 (6 words), rows 128..131 full
    for (int i = tid; i < 128*6; i += 256){
        int r = i/6, w = i - r*6;
        *(uint32_t*)(sm + OFF_G + (uint32_t)(r*156 + 150 + w)*4) = 0u;
    }
    for (int i = tid; i < 4*156; i += 256)
        *(uint32_t*)(sm + OFF_G + (uint32_t)(128*156 + i)*4) = 0u;
    __syncthreads();

    // gather G (fp32 -> fp16), row stride 624 B
    {
        const int* stok = (const int*)sm;
        for (int i = tid; i < 128*75; i += 256){
            int r = i/75, q = i - r*75;
            float4 v = __ldg((const float4*)(emb + (size_t)stok[r]*D) + q);
            uint2 t;
            __half2 h01 = __floats2half2_rn(v.x, v.y);
            __half2 h23 = __floats2half2_rn(v.z, v.w);
            t.x = *(uint32_t*)&h01; t.y = *(uint32_t*)&h23;
            *(uint2*)(sm + OFF_G + (uint32_t)r*624 + (uint32_t)q*8) = t;
        }
    }

    const int r = lane >> 2;
    const uint32_t gbase = sb + OFF_G + (uint32_t)(mw*32 + (lane & 15))*624
                                      + (uint32_t)((lane >> 4) << 4);
    float* red = (float*)(sm + OFF_RED);    // overlays ring slots 4..5 (quiescent)

    for (int oph = 0; oph < 2; oph++){
        float acc[10][2][4];
        #pragma unroll
        for (int t = 0; t < 10; t++)
            #pragma unroll
            for (int mt = 0; mt < 2; mt++)
                acc[t][mt][0] = acc[t][mt][1] = acc[t][mt][2] = acc[t][mt][3] = 0.f;

        for (int p = 0; p < 47; p++){
            if (p < 46) asm volatile("cp.async.wait_group 2;" ::: "memory");
            else        asm volatile("cp.async.wait_group 1;" ::: "memory");
            __syncthreads();
            if (p < 45){
                load_chunk(sb, oph, 2*p + 4, tid);
                load_chunk(sb, oph, 2*p + 5, tid);
            } else if (p == 45){
                load_chunk(sb, oph, 94, tid);
            }
            if (ng == 0){
                do_chunk_t<10>(sb, gbase, 2*p,     acc, lane, jb);
                do_chunk_t<10>(sb, gbase, 2*p + 1, acc, lane, jb);
            } else {
                do_chunk_t<9>(sb, gbase, 2*p,     acc, lane, jb);
                do_chunk_t<9>(sb, gbase, 2*p + 1, acc, lane, jb);
            }
        }
        // tail chunk 94
        asm volatile("cp.async.wait_group 0;" ::: "memory");
        __syncthreads();
        if (ng == 0) do_chunk_t<10>(sb, gbase, 94, acc, lane, jb);
        else         do_chunk_t<9> (sb, gbase, 94, acc, lane, jb);
        __syncthreads();

        // prefetch next phase's chunks 0..3 into ring slots 0..3 (disjoint from red)
        if (oph == 0){
            load_chunk(sb, 1, 0, tid);
            load_chunk(sb, 1, 1, tid);
            load_chunk(sb, 1, 2, tid);
            load_chunk(sb, 1, 3, tid);
        }

        // ---- maxpool over t ----
        // rows covered: mt0 -> mw*32+r, +8 (always < 124); mt1 -> +16 (<124), +24 (mask)
        const int gsl = 10 - ng;
        bool v2 = (mw*32 + 24 + r) < LT;
        #pragma unroll
        for (int t = 0; t < 10; t++) if (t < gsl){
            float m0 = fmaxf(acc[t][0][0], acc[t][0][2]);
            float m1 = fmaxf(acc[t][0][1], acc[t][0][3]);
            m0 = fmaxf(m0, fmaxf(acc[t][1][0], v2 ? acc[t][1][2] : -3.4e38f));
            m1 = fmaxf(m1, fmaxf(acc[t][1][1], v2 ? acc[t][1][3] : -3.4e38f));
            #pragma unroll
            for (int off = 4; off <= 16; off <<= 1){
                m0 = fmaxf(m0, __shfl_xor_sync(0xffffffffu, m0, off));
                m1 = fmaxf(m1, __shfl_xor_sync(0xffffffffu, m1, off));
            }
            if (lane < 4){
                red[mw*152 + (jb + t)*8 + 2*lane]     = m0;
                red[mw*152 + (jb + t)*8 + 2*lane + 1] = m1;
            }
        }
        __syncthreads();
        if (tid < 152){
            float m = fmaxf(fmaxf(red[tid], red[152 + tid]),
                            fmaxf(red[304 + tid], red[456 + tid]));
            int o = oph*152 + tid;
            if (o < D) d_conc[(size_t)n*600 + o] = m + d_biasf[o];
        }
        __syncthreads();   // red consumed before next phase's compute reuses slots 4..5
    }
}

// ---------------- MLP epilogue: 4 bags per CTA, 320 threads (1 o per thread) ----------------
__global__ void __launch_bounds__(320,1)
mlp_kernel(const float* __restrict__ mention,
           const float* __restrict__ W2, const float* __restrict__ b2,
           const float* __restrict__ W3, const float* __restrict__ b3,
           float* __restrict__ out){
    __shared__ float cs[4*600], hs[4*300];
    const int nb = blockIdx.x*4, tid = threadIdx.x;
    for (int i = tid; i < 1200; i += 320){
        int b = i/300, o = i - b*300;
        cs[b*600 + o]       = d_conc[(size_t)(nb+b)*600 + o];
        cs[b*600 + 300 + o] = mention[(size_t)(nb+b)*300 + o];
    }
    __syncthreads();
    if (tid < D){
        const int o = tid;
        float a0 = b2[o], a1 = a0, a2 = a0, a3 = a0;
        for (int j = 0; j < 600; j++){
            float w = __ldg(&W2[(size_t)j*D + o]);
            a0 = fmaf(cs[j], w, a0);       a1 = fmaf(cs[600+j], w, a1);
            a2 = fmaf(cs[1200+j], w, a2);  a3 = fmaf(cs[1800+j], w, a3);
        }
        hs[o] = tanhf(a0); hs[300+o] = tanhf(a1);
        hs[600+o] = tanhf(a2); hs[900+o] = tanhf(a3);
    }
    __syncthreads();
    if (tid < D){
        const int o = tid;
        float a0 = b3[o], a1 = a0, a2 = a0, a3 = a0;
        for (int j = 0; j < D; j++){
            float w = __ldg(&W3[(size_t)j*D + o]);
            a0 = fmaf(hs[j], w, a0);      a1 = fmaf(hs[300+j], w, a1);
            a2 = fmaf(hs[600+j], w, a2);  a3 = fmaf(hs[900+j], w, a3);
        }
        out[(size_t)nb*D + o] = a0;       out[(size_t)(nb+1)*D + o] = a1;
        out[(size_t)(nb+2)*D + o] = a2;   out[(size_t)(nb+3)*D + o] = a3;
    }
}

extern "C" void kernel_launch(void* const* d_in, const int* in_sizes, int n_in,
                              void* d_out, int out_size){
    const int*   tok     = (const int*)  d_in[0];
    const float* mention = (const float*)d_in[1];
    const float* emb     = (const float*)d_in[2];
    const float* W1      = (const float*)d_in[3];
    const float* b1      = (const float*)d_in[4];
    const float* conv_w  = (const float*)d_in[5];
    const float* conv_b  = (const float*)d_in[6];
    const float* W2      = (const float*)d_in[7];
    const float* b2      = (const float*)d_in[8];
    const float* W3      = (const float*)d_in[9];
    const float* b3      = (const float*)d_in[10];
    float* out = (float*)d_out;

    cudaFuncSetAttribute(main_kernel, cudaFuncAttributeMaxDynamicSharedMemorySize, SMEM_T);
    prep_kernel<<<(KW*D*D + 255)/256, 256>>>(conv_w);
    bias_kernel<<<D, 128>>>(conv_w, conv_b, b1);
    fuse_kernel<<<KW*38, 320>>>(W1);
    main_kernel<<<1024, 256, SMEM_T>>>(tok, emb);
    mlp_kernel<<<256, 320>>>(mention, W2, b2, W3, b3, out);
}